// round 7
// baseline (speedup 1.0000x reference)
#include <cuda_runtime.h>
#include <cstdint>

#define N_ROWS 16384
#define K_CODES 4096
#define D_DIM 512

#define TILE_M 128
#define TILE_N 128
#define NTILES 32

#define B_OFF 65536
#define B_STAGE 65536
#define CN_OFF (65536 * 3)
#define DYN_BYTES (CN_OFF + K_CODES * 4)   // 212992

#define MARGIN 1.0e-3f
#define MAX_CAND 64

#define SZQ (127.0f / 6.0f)                 // z quant scale
#define SCQ (127.0f * 4096.0f)              // codebook quant scale
#define MS  (-2.0f * (6.0f / 127.0f) / (127.0f * 4096.0f))

// -------- scratch (static device globals; no allocation) --------
__device__ int      g_zq[N_ROWS * 128];     // z int8 packed, 8 MB
__device__ int      g_cq[K_CODES * 128];    // codebook int8 packed, 2 MB
__device__ float    g_znorm[N_ROWS];
__device__ float    g_cnorm[K_CODES];
__device__ int      g_idx[N_ROWS];
__device__ float    g_partial[N_ROWS];
__device__ int      g_cand[N_ROWS * MAX_CAND];
__device__ unsigned g_cnt[N_ROWS];

// -------- helpers --------
__device__ __forceinline__ unsigned smem_u32(const void* p){
    unsigned a;
    asm("{ .reg .u64 t; cvta.to.shared.u64 t, %1; cvt.u32.u64 %0, t; }" : "=r"(a) : "l"(p));
    return a;
}
__device__ __forceinline__ void cp16(unsigned s, const void* g){
    asm volatile("cp.async.cg.shared.global [%0], [%1], 16;" :: "r"(s), "l"(g) : "memory");
}
__device__ __forceinline__ void ldsm4(unsigned& r0, unsigned& r1, unsigned& r2, unsigned& r3,
                                      unsigned addr){
    asm volatile("ldmatrix.sync.aligned.m8n8.x4.shared.b16 {%0,%1,%2,%3}, [%4];"
        : "=r"(r0), "=r"(r1), "=r"(r2), "=r"(r3) : "r"(addr));
}
__device__ __forceinline__ void imma(int& c0, int& c1, int& c2, int& c3,
                                     unsigned a0, unsigned a1, unsigned a2, unsigned a3,
                                     unsigned b0, unsigned b1){
    asm volatile(
        "mma.sync.aligned.m16n8k32.row.col.s32.s8.s8.s32 "
        "{%0,%1,%2,%3}, {%4,%5,%6,%7}, {%8,%9}, {%0,%1,%2,%3};"
        : "+r"(c0), "+r"(c1), "+r"(c2), "+r"(c3)
        : "r"(a0), "r"(a1), "r"(a2), "r"(a3), "r"(b0), "r"(b1));
}
__device__ __forceinline__ unsigned enc_f(float f){
    unsigned b = __float_as_uint(f);
    return (b & 0x80000000u) ? ~b : (b | 0x80000000u);
}
__device__ __forceinline__ float dec_f(unsigned e){
    return (e & 0x80000000u) ? __uint_as_float(e ^ 0x80000000u) : __uint_as_float(~e);
}
__device__ __forceinline__ int q8(float v, float s){
    float t = fminf(fmaxf(v * s, -127.0f), 127.0f);
    return __float2int_rn(t);
}
__device__ __forceinline__ int pack4(int a, int b, int c, int d){
    return (a & 255) | ((b & 255) << 8) | ((c & 255) << 16) | ((d & 255) << 24);
}

// -------- prep_z: fused fp64 row norm + int8 quant + cnt init --------
__global__ void prep_z_kernel(const float* __restrict__ z){
    int w = (blockIdx.x * blockDim.x + threadIdx.x) >> 5;
    int lane = threadIdx.x & 31;
    if (w >= N_ROWS) return;
    const float4* r4 = (const float4*)(z + (size_t)w * D_DIM);
    double acc = 0.0;
    #pragma unroll
    for (int j = 0; j < 4; j++){
        int widx = j * 32 + lane;
        float4 v = r4[widx];
        acc += (double)v.x * v.x + (double)v.y * v.y
             + (double)v.z * v.z + (double)v.w * v.w;
        g_zq[w * 128 + widx] = pack4(q8(v.x, SZQ), q8(v.y, SZQ), q8(v.z, SZQ), q8(v.w, SZQ));
    }
    #pragma unroll
    for (int o = 16; o > 0; o >>= 1) acc += __shfl_down_sync(0xffffffffu, acc, o);
    if (lane == 0){ g_znorm[w] = (float)acc; g_cnt[w] = 0u; }
}

// -------- prep_c: fused fp64 code norm + int8 quant --------
__global__ void prep_c_kernel(const float* __restrict__ cb){
    int w = (blockIdx.x * blockDim.x + threadIdx.x) >> 5;
    int lane = threadIdx.x & 31;
    if (w >= K_CODES) return;
    const float4* r4 = (const float4*)(cb + (size_t)w * D_DIM);
    double acc = 0.0;
    #pragma unroll
    for (int j = 0; j < 4; j++){
        int widx = j * 32 + lane;
        float4 v = r4[widx];
        acc += (double)v.x * v.x + (double)v.y * v.y
             + (double)v.z * v.z + (double)v.w * v.w;
        g_cq[w * 128 + widx] = pack4(q8(v.x, SCQ), q8(v.y, SCQ), q8(v.z, SCQ), q8(v.w, SCQ));
    }
    #pragma unroll
    for (int o = 16; o > 0; o >>= 1) acc += __shfl_down_sync(0xffffffffu, acc, o);
    if (lane == 0) g_cnorm[w] = (float)acc;
}

// -------- tile loaders (XOR-chunk-swizzled 16B units) --------
__device__ __forceinline__ void load_A(unsigned smA, int rowbase, int tid){
    const char* src = (const char*)g_zq;
    #pragma unroll
    for (int i = 0; i < 16; i++){
        int f = tid + i * 256;
        int r = f >> 5, c = f & 31;
        unsigned dst = smA + (unsigned)(r * 512 + ((c ^ ((r >> 2) & 7)) << 4));
        cp16(dst, src + (size_t)(rowbase + r) * 512 + (c << 4));
    }
}
__device__ __forceinline__ void load_B(unsigned smB, int nt, int tid){
    const char* src = (const char*)g_cq;
    #pragma unroll
    for (int i = 0; i < 16; i++){
        int f = tid + i * 256;
        int r = f >> 5, c = f & 31;
        unsigned dst = smB + (unsigned)(r * 512 + ((c ^ ((r >> 2) & 7)) << 4));
        cp16(dst, src + (size_t)(nt * TILE_N + r) * 512 + (c << 4));
    }
}

// -------- main IMMA int8 kernel: distances + candidate screening --------
extern __shared__ char sm_dyn[];
__global__ __launch_bounds__(256, 1)
void vq_imma_kernel()
{
    __shared__ unsigned s_tile[TILE_M];
    __shared__ float    s_run[TILE_M];

    const int tid  = threadIdx.x;
    const int lane = tid & 31;
    const int warp = tid >> 5;
    const int wm   = warp & 3;        // 4 warps along M (32 rows each)
    const int wn   = warp >> 2;       // 2 warps along N (64 cols each)
    const int rowbase = blockIdx.x * TILE_M;
    const unsigned smA = smem_u32(sm_dyn);
    float* cn_sm = (float*)(sm_dyn + CN_OFF);

    // prologue
    load_A(smA, rowbase, tid);
    load_B(smA + B_OFF, 0, tid);
    asm volatile("cp.async.commit_group;" ::: "memory");
    for (int i = tid; i < K_CODES; i += 256) cn_sm[i] = g_cnorm[i];
    if (tid < TILE_M){ s_tile[tid] = 0xFFFFFFFFu; s_run[tid] = 3.4e38f; }

    // ldmatrix per-lane row assignments
    const int hi = lane >> 4;                 // chunk +0 / +1 within k-step
    int  rA[2];  unsigned baseA[2], swA[2];
    #pragma unroll
    for (int mb = 0; mb < 2; mb++){
        rA[mb] = wm * 32 + mb * 16 + (lane & 15);
        baseA[mb] = smA + (unsigned)(rA[mb] * 512);
        swA[mb] = (unsigned)((rA[mb] >> 2) & 7);
    }
    int  rB[4];  unsigned offB[4], swB[4];
    #pragma unroll
    for (int np = 0; np < 4; np++){
        rB[np] = wn * 64 + np * 16 + (lane & 15);
        offB[np] = (unsigned)(rB[np] * 512);
        swB[np] = (unsigned)((rB[np] >> 2) & 7);
    }

    int acc[2][8][4];
    #pragma unroll
    for (int mb = 0; mb < 2; mb++)
        #pragma unroll
        for (int nb = 0; nb < 8; nb++)
            #pragma unroll
            for (int r = 0; r < 4; r++) acc[mb][nb][r] = 0;

    const int rowq = lane >> 2;   // row within m16 tile (0..7)
    const int colq = lane & 3;

    for (int nt = 0; nt < NTILES; nt++){
        if (nt + 1 < NTILES){
            load_B(smA + B_OFF + (unsigned)(((nt + 1) & 1) * B_STAGE), nt + 1, tid);
            asm volatile("cp.async.commit_group;" ::: "memory");
            asm volatile("cp.async.wait_group 1;" ::: "memory");
        } else {
            asm volatile("cp.async.wait_group 0;" ::: "memory");
        }
        __syncthreads();

        const unsigned smB = smA + B_OFF + (unsigned)((nt & 1) * B_STAGE);

        #pragma unroll 2
        for (int ks = 0; ks < 16; ks++){
            const unsigned ch = (unsigned)(2 * ks + hi);
            unsigned aF[2][4], bF[4][4];
            #pragma unroll
            for (int mb = 0; mb < 2; mb++)
                ldsm4(aF[mb][0], aF[mb][1], aF[mb][2], aF[mb][3],
                      baseA[mb] + ((ch ^ swA[mb]) << 4));
            #pragma unroll
            for (int np = 0; np < 4; np++)
                ldsm4(bF[np][0], bF[np][1], bF[np][2], bF[np][3],
                      smB + offB[np] + ((ch ^ swB[np]) << 4));
            #pragma unroll
            for (int mb = 0; mb < 2; mb++)
                #pragma unroll
                for (int np = 0; np < 4; np++){
                    imma(acc[mb][np*2+0][0], acc[mb][np*2+0][1],
                         acc[mb][np*2+0][2], acc[mb][np*2+0][3],
                         aF[mb][0], aF[mb][1], aF[mb][2], aF[mb][3],
                         bF[np][0], bF[np][2]);
                    imma(acc[mb][np*2+1][0], acc[mb][np*2+1][1],
                         acc[mb][np*2+1][2], acc[mb][np*2+1][3],
                         aF[mb][0], aF[mb][1], aF[mb][2], aF[mb][3],
                         bF[np][1], bF[np][3]);
                }
        }

        // ---- epilogue for tile nt ----
        // acc[mb][nb][r]: row = wm*32+mb*16+rowq+8*(r>=2), col = wn*64+nb*8+colq*2+(r&1)
        float vmin[2][2];   // [mb][half: r<2 vs r>=2]
        #pragma unroll
        for (int mb = 0; mb < 2; mb++){ vmin[mb][0] = 3.4e38f; vmin[mb][1] = 3.4e38f; }
        #pragma unroll
        for (int mb = 0; mb < 2; mb++)
            #pragma unroll
            for (int nb = 0; nb < 8; nb++)
                #pragma unroll
                for (int r = 0; r < 4; r++){
                    int colg = nt * TILE_N + wn * 64 + nb * 8 + colq * 2 + (r & 1);
                    float fv = fmaf(MS, (float)acc[mb][nb][r], cn_sm[colg]);
                    acc[mb][nb][r] = __float_as_int(fv);
                    vmin[mb][r >> 1] = fminf(vmin[mb][r >> 1], fv);
                }
        // reduce row-min across the 4 lanes sharing each row, then atomicMin
        #pragma unroll
        for (int mb = 0; mb < 2; mb++)
            #pragma unroll
            for (int h = 0; h < 2; h++){
                float m = vmin[mb][h];
                m = fminf(m, __shfl_xor_sync(0xffffffffu, m, 1));
                m = fminf(m, __shfl_xor_sync(0xffffffffu, m, 2));
                if (colq == 0)
                    atomicMin(&s_tile[wm * 32 + mb * 16 + h * 8 + rowq], enc_f(m));
            }
        __syncthreads();
        if (tid < TILE_M){
            s_run[tid] = fminf(s_run[tid], dec_f(s_tile[tid]));
            s_tile[tid] = 0xFFFFFFFFu;
        }
        __syncthreads();
        #pragma unroll
        for (int mb = 0; mb < 2; mb++)
            #pragma unroll
            for (int h = 0; h < 2; h++){
                int rowl = wm * 32 + mb * 16 + h * 8 + rowq;
                float thr = s_run[rowl] + MARGIN;
                int rowg = rowbase + rowl;
                #pragma unroll
                for (int nb = 0; nb < 8; nb++)
                    #pragma unroll
                    for (int rr = 0; rr < 2; rr++){
                        int r = h * 2 + rr;
                        if (__int_as_float(acc[mb][nb][r]) < thr){
                            int colg = nt * TILE_N + wn * 64 + nb * 8 + colq * 2 + rr;
                            unsigned slot = atomicAdd(&g_cnt[rowg], 1u);
                            if (slot < MAX_CAND)
                                g_cand[rowg * MAX_CAND + slot] = colg;
                        }
                        acc[mb][nb][r] = 0;
                    }
            }
    }
}

// -------- exact fp32 rescue (coalesced; warp per candidate) --------
__global__ __launch_bounds__(128, 8)
void rescue_kernel(const float* __restrict__ z, const float* __restrict__ cb)
{
    __shared__ __align__(16) float s_z[D_DIM];
    __shared__ float s_best[4];
    __shared__ int   s_bi[4];

    const int row  = blockIdx.x;
    const int tid  = threadIdx.x;
    const int warp = tid >> 5;
    const int lane = tid & 31;
    const unsigned cnt = g_cnt[row];
    const float zn = g_znorm[row];

    ((float4*)s_z)[tid] = ((const float4*)(z + (size_t)row * D_DIM))[tid];
    __syncthreads();

    const float4* z4 = (const float4*)s_z;
    float best = 3.4e38f;
    int bi = 0x7fffffff;

    if (cnt <= MAX_CAND){
        for (int k = warp; k < (int)cnt; k += 4){
            int cix = g_cand[row * MAX_CAND + k];
            const float4* c4 = (const float4*)(cb + (size_t)cix * D_DIM);
            float acc = 0.0f;
            #pragma unroll
            for (int i = 0; i < 4; i++){
                float4 cv = c4[i * 32 + lane];
                float4 zv = z4[i * 32 + lane];
                acc = fmaf(zv.x, cv.x, acc);
                acc = fmaf(zv.y, cv.y, acc);
                acc = fmaf(zv.z, cv.z, acc);
                acc = fmaf(zv.w, cv.w, acc);
            }
            #pragma unroll
            for (int o = 16; o > 0; o >>= 1)
                acc += __shfl_down_sync(0xffffffffu, acc, o);
            if (lane == 0){
                float d = fmaf(-2.0f, acc, __fadd_rn(zn, g_cnorm[cix]));
                if (d < best || (d == best && cix < bi)){ best = d; bi = cix; }
            }
        }
    } else {
        for (int cix = warp; cix < K_CODES; cix += 4){
            const float4* c4 = (const float4*)(cb + (size_t)cix * D_DIM);
            float acc = 0.0f;
            #pragma unroll
            for (int i = 0; i < 4; i++){
                float4 cv = c4[i * 32 + lane];
                float4 zv = z4[i * 32 + lane];
                acc = fmaf(zv.x, cv.x, acc);
                acc = fmaf(zv.y, cv.y, acc);
                acc = fmaf(zv.z, cv.z, acc);
                acc = fmaf(zv.w, cv.w, acc);
            }
            #pragma unroll
            for (int o = 16; o > 0; o >>= 1)
                acc += __shfl_down_sync(0xffffffffu, acc, o);
            if (lane == 0){
                float d = fmaf(-2.0f, acc, __fadd_rn(zn, g_cnorm[cix]));
                if (d < best || (d == best && cix < bi)){ best = d; bi = cix; }
            }
        }
    }

    if (lane == 0){ s_best[warp] = best; s_bi[warp] = bi; }
    __syncthreads();
    if (tid == 0){
        float bv = s_best[0]; int bix = s_bi[0];
        #pragma unroll
        for (int w = 1; w < 4; w++){
            float vv = s_best[w]; int ii = s_bi[w];
            if (vv < bv || (vv == bv && ii < bix)){ bv = vv; bix = ii; }
        }
        g_idx[row] = bix;
        g_partial[row] = bv;
    }
}

// -------- gather z_q + indices --------
__global__ void gather_kernel(const float* __restrict__ cb, float* __restrict__ out)
{
    int row = blockIdx.x, t = threadIdx.x;
    int id = g_idx[row];
    float4 v = ((const float4*)(cb + (size_t)id * D_DIM))[t];
    ((float4*)(out + (size_t)row * D_DIM))[t] = v;
    if (t == 0) out[(size_t)N_ROWS * D_DIM + row] = (float)id;
}

// -------- final loss --------
__global__ void loss_kernel(float* __restrict__ out){
    __shared__ double red[256];
    int t = threadIdx.x;
    double a = 0.0;
    for (int j = t; j < N_ROWS; j += 256) a += (double)g_partial[j];
    red[t] = a; __syncthreads();
    #pragma unroll
    for (int s = 128; s > 0; s >>= 1){
        if (t < s) red[t] += red[t + s];
        __syncthreads();
    }
    if (t == 0){
        float v = (float)(red[0] / ((double)N_ROWS * (double)D_DIM));
        out[(size_t)N_ROWS * D_DIM + N_ROWS] = __fadd_rn(v, 0.25f * v);
    }
}

extern "C" void kernel_launch(void* const* d_in, const int* in_sizes, int n_in,
                              void* d_out, int out_size)
{
    const float* z  = (const float*)d_in[0];   // [16384, 512]
    const float* cb = (const float*)d_in[1];   // [4096, 512]
    float* out = (float*)d_out;                // [z_q (N*D)] [idx (N)] [loss (1)]

    cudaFuncSetAttribute(vq_imma_kernel,
                         cudaFuncAttributeMaxDynamicSharedMemorySize, DYN_BYTES);

    prep_z_kernel<<<N_ROWS / 8, 256>>>(z);
    prep_c_kernel<<<K_CODES / 8, 256>>>(cb);
    vq_imma_kernel<<<N_ROWS / TILE_M, 256, DYN_BYTES>>>();
    rescue_kernel<<<N_ROWS, 128>>>(z, cb);
    gather_kernel<<<N_ROWS, 128>>>(cb, out);
    loss_kernel<<<1, 256>>>(out);
}